// round 16
// baseline (speedup 1.0000x reference)
#include <cuda_runtime.h>
#include <cuda_bf16.h>
#include <math.h>

#define BB 32
#define DD 8732
#define OO 8
#define CC 21
#define LL 32
#define KK 256
#define NCE 35     // chunks per batch (35*256 >= 8732)
#define NPART (BB*NCE)
#define HSTR 257   // padded per-warp histogram stride

// ---------------- device scratch ----------------
__device__ unsigned char d_ct[BB*DD];
__device__ float  d_ceneg[BB*DD];
__device__ unsigned long long d_bestkey[NPART*OO];
__device__ double d_pll[NPART], d_plp[NPART], d_pce[NPART];
__device__ int    d_npb[NPART];
__device__ double d_topksum[BB];
__device__ double d_pdesk[KK], d_ptrips[KK];
__device__ int    d_pnpp[KK], d_pnnp[KK], d_ptc[KK];
__device__ int2   d_slot[KK];
__device__ unsigned g_done;   // zero-init; reset by final block each run

// fast exp on the FMA pipe (inputs are x - max <= 0)
__device__ __forceinline__ float fexp(float x) {
    x = fmaxf(x, -80.0f);
    float y = x * 1.442695040888963f;
    float n = rintf(y);
    float f = y - n;
    float p = 1.54035303933816e-4f;
    p = fmaf(p, f, 1.33335581464284e-3f);
    p = fmaf(p, f, 9.61812910762848e-3f);
    p = fmaf(p, f, 5.55041086648216e-2f);
    p = fmaf(p, f, 2.40226506959101e-1f);
    p = fmaf(p, f, 6.93147180559945e-1f);
    p = fmaf(p, f, 1.0f);
    return __int_as_float(__float_as_int(p) + (((int)n) << 23));
}

// ---------------- kernel 1: lse + per-chunk match keys ----------------
__global__ void k_lsematch(const float* __restrict__ conf,
                           const float* __restrict__ dbox,
                           const float* __restrict__ tgt) {
    const int b = blockIdx.y, c = blockIdx.x;
    const int tid = threadIdx.x;
    const int d = c*256 + tid;
    __shared__ float sconf[256*CC];
    __shared__ float tx1[OO], ty1[OO], tx2[OO], ty2[OO], ta[OO];

    if (tid < OO) {
        const float* p = tgt + (size_t)(b*OO + tid)*9;
        tx1[tid] = p[0]; ty1[tid] = p[1]; tx2[tid] = p[2]; ty2[tid] = p[3];
        ta[tid]  = (p[2]-p[0])*(p[3]-p[1]);
    }
    {
        int d0 = c * 256;
        int nblk = DD - d0; if (nblk > 256) nblk = 256;
        int nflt = nblk * CC;
        const float4* c4 = (const float4*)(conf + ((size_t)b*DD + d0)*CC);
        float4* s4 = (float4*)sconf;
        for (int i = tid; i < (nflt >> 2); i += 256) s4[i] = c4[i];
    }
    __syncthreads();

    unsigned long long bk[OO];
#pragma unroll
    for (int t = 0; t < OO; t++) bk[t] = 0ull;

    if (d < DD) {
        const float* v = sconf + tid*CC;
        float m = v[0];
#pragma unroll
        for (int cc = 1; cc < CC; cc++) m = fmaxf(m, v[cc]);
        float s = 0.0f;
#pragma unroll
        for (int cc = 0; cc < CC; cc++) s += fexp(v[cc] - m);
        d_ceneg[(size_t)b*DD + d] = m + logf(s) - v[0];

        float4 db = __ldg((const float4*)(dbox + d*4));
        float px1 = db.x - db.z*0.5f, py1 = db.y - db.w*0.5f;
        float px2 = db.x + db.z*0.5f, py2 = db.y + db.w*0.5f;
        float pa = (px2-px1)*(py2-py1);
#pragma unroll
        for (int t = 0; t < OO; t++) {
            float ix = fmaxf(fminf(tx2[t], px2) - fmaxf(tx1[t], px1), 0.0f);
            float iy = fmaxf(fminf(ty2[t], py2) - fmaxf(ty1[t], py1), 0.0f);
            float inter = ix * iy;
            float iou = inter / (ta[t] + pa - inter);
            bk[t] = ((unsigned long long)__float_as_uint(iou) << 32) |
                    (unsigned long long)(0xFFFFFFFFu - (unsigned)d);
        }
    }

    __shared__ unsigned long long wk[8][OO];
    int wid = tid >> 5, lane = tid & 31;
#pragma unroll
    for (int t = 0; t < OO; t++) {
        unsigned long long k = bk[t];
#pragma unroll
        for (int s = 16; s > 0; s >>= 1) {
            unsigned long long o = __shfl_down_sync(0xffffffffu, k, s);
            if (o > k) k = o;
        }
        if (lane == 0) wk[wid][t] = k;
    }
    __syncthreads();
    if (tid < OO) {
        unsigned long long k = 0ull;
#pragma unroll
        for (int w = 0; w < 8; w++) if (wk[w][tid] > k) k = wk[w][tid];
        d_bestkey[((size_t)b*NCE + c)*OO + tid] = k;
    }
}

// ---------------- kernel 2: encce ----------------
__global__ void k_encce(const float* __restrict__ loc,
                        const float* __restrict__ pose,
                        const float* __restrict__ dbox,
                        const float* __restrict__ tgt,
                        const float* __restrict__ conf) {
    const int b = blockIdx.y;
    const int tid = threadIdx.x;
    const int d = blockIdx.x * 256 + tid;

    __shared__ float tx1[OO], ty1[OO], tx2[OO], ty2[OO], ta[OO];
    __shared__ float tpz[OO][3];
    __shared__ int   tlab[OO], bestd[OO];

    if (tid < OO) {
        const float* p = tgt + (size_t)(b*OO + tid)*9;
        tx1[tid] = p[0]; ty1[tid] = p[1]; tx2[tid] = p[2]; ty2[tid] = p[3];
        ta[tid]  = (p[2]-p[0])*(p[3]-p[1]);
        tlab[tid] = (int)p[4];
        tpz[tid][0] = p[5]; tpz[tid][1] = p[6]; tpz[tid][2] = p[7];
        unsigned long long k = 0ull;
        for (int c = 0; c < NCE; c++) {
            unsigned long long o = d_bestkey[((size_t)b*NCE + c)*OO + tid];
            if (o > k) k = o;
        }
        bestd[tid] = (int)(0xFFFFFFFFu - (unsigned)(k & 0xFFFFFFFFull));
    }
    __syncthreads();

    float ll = 0.0f, lp = 0.0f, cepos = 0.0f;
    int np = 0;
    if (d < DD) {
        int idx = b*DD + d;
        float4 db = __ldg((const float4*)(dbox + d*4));
        float px1 = db.x - db.z*0.5f, py1 = db.y - db.w*0.5f;
        float px2 = db.x + db.z*0.5f, py2 = db.y + db.w*0.5f;
        float pa = (px2-px1)*(py2-py1);
        float mv = -1.0f; int mt = 0;
#pragma unroll
        for (int t = 0; t < OO; t++) {
            float ix = fmaxf(fminf(tx2[t], px2) - fmaxf(tx1[t], px1), 0.0f);
            float iy = fmaxf(fminf(ty2[t], py2) - fmaxf(ty1[t], py1), 0.0f);
            float inter = ix * iy;
            float iou = inter / (ta[t] + pa - inter);
            if (iou > mv) { mv = iou; mt = t; }
        }
#pragma unroll
        for (int t = 0; t < OO; t++) {
            if (bestd[t] == d) { mv = 2.0f; mt = t; }
        }
        int cf = (mv < 0.5f) ? 0 : (tlab[mt] + 1);
        d_ct[idx] = (unsigned char)(cf | (mt << 5));

        if (cf > 0) {
            np = 1;
            float g0 = ((tx1[mt] + tx2[mt])*0.5f - db.x) / (0.1f * db.z);
            float g1 = ((ty1[mt] + ty2[mt])*0.5f - db.y) / (0.1f * db.w);
            float g2 = logf((tx2[mt] - tx1[mt]) / db.z) / 0.2f;
            float g3 = logf((ty2[mt] - ty1[mt]) / db.w) / 0.2f;
            float g[4] = {g0, g1, g2, g3};
#pragma unroll
            for (int i = 0; i < 4; i++) {
                float dd_ = loc[(size_t)idx*4 + i] - g[i];
                float ad = fabsf(dd_);
                ll += (ad < 1.0f) ? (0.5f*dd_*dd_) : (ad - 0.5f);
            }
#pragma unroll
            for (int i = 0; i < 3; i++) {
                float e = pose[(size_t)idx*3 + i] - tpz[mt][i];
                lp += e*e;
            }
            float vneg = d_ceneg[idx];
            float v0  = __ldg(conf + (size_t)idx*CC);
            float vcf = __ldg(conf + (size_t)idx*CC + cf);
            cepos = vneg + v0 - vcf;
            d_ceneg[idx] = 0.0f;
        }
    }

    double rll = (double)ll, rlp = (double)lp, rce = (double)cepos;
    int rnp = np;
#pragma unroll
    for (int s = 16; s > 0; s >>= 1) {
        rll += __shfl_down_sync(0xffffffffu, rll, s);
        rlp += __shfl_down_sync(0xffffffffu, rlp, s);
        rce += __shfl_down_sync(0xffffffffu, rce, s);
        rnp += __shfl_down_sync(0xffffffffu, rnp, s);
    }
    __shared__ double wll[8], wlp[8], wce[8];
    __shared__ int wnp[8];
    int wid = tid >> 5, lane = tid & 31;
    if (lane == 0) { wll[wid] = rll; wlp[wid] = rlp; wce[wid] = rce; wnp[wid] = rnp; }
    __syncthreads();
    if (tid == 0) {
        double a = 0.0, b2 = 0.0, c2 = 0.0; int nn = 0;
#pragma unroll
        for (int w = 0; w < 8; w++) { a += wll[w]; b2 += wlp[w]; c2 += wce[w]; nn += wnp[w]; }
        int part = b*NCE + blockIdx.x;
        d_pll[part] = a; d_plp[part] = b2; d_pce[part] = c2;
        d_npb[part] = nn;
    }
}

// ---------------- kernel 3: topk (blocks 0..31) + map (blocks 32..) ----------------
struct STK {
    double wsg[8];
    float sce[DD];
    int hist[8*HSTR];
    int histc[256];
    int wcg[8];
    unsigned s_prefix; int s_rem; int s_k;
};
struct SMAP {
    int wlo[8], wto[8], wcnt[8], woff[8], wcnt2[8], woff2[8];
    int s_off, s_tot;
};

__global__ void k_topkmap() {
    __shared__ __align__(16) unsigned char sbuf[sizeof(STK)];
    const int tid = threadIdx.x;
    const int wid = tid >> 5, lane = tid & 31;

    if (blockIdx.x < BB) {
        STK* sm = (STK*)sbuf;
        const int b = blockIdx.x;
        {
            int s = (tid < NCE) ? d_npb[b*NCE + tid] : 0;
#pragma unroll
            for (int st = 16; st > 0; st >>= 1) s += __shfl_down_sync(0xffffffffu, s, st);
            if (lane == 0) sm->wcg[wid] = s;
        }
        {
            const float4* ce4 = (const float4*)(d_ceneg + (size_t)b * DD);
            float4* s4 = (float4*)sm->sce;
            for (int i = tid; i < DD/4; i += 256) s4[i] = ce4[i];
        }
        __syncthreads();
        if (tid == 0) {
            int t = 0;
#pragma unroll
            for (int w = 0; w < 8; w++) t += sm->wcg[w];
            int k = t * 3; if (k > DD) k = DD;
            sm->s_k = k; sm->s_prefix = 0u; sm->s_rem = k;
        }
        __syncthreads();
        if (sm->s_k <= 0) { if (tid == 0) d_topksum[b] = 0.0; return; }

#pragma unroll
        for (int pass = 3; pass >= 1; pass--) {
            for (int i = tid; i < 8*HSTR; i += 256) sm->hist[i] = 0;
            __syncthreads();
            const unsigned pref = sm->s_prefix;
            const int sh = pass * 8;
            int* myhist = sm->hist + wid*HSTR;
            for (int d = tid; d < DD; d += 256) {
                unsigned u = __float_as_uint(sm->sce[d]);
                bool ok = (pass == 3) || ((u >> (sh + 8)) == (pref >> (sh + 8)));
                if (ok) {
                    int dig = (u >> sh) & 255;
                    unsigned act = __activemask();
                    unsigned mm = __match_any_sync(act, dig);
                    if (lane == (__ffs(mm) - 1))
                        atomicAdd(&myhist[dig], __popc(mm));
                }
            }
            __syncthreads();
            {
                int s2 = 0;
#pragma unroll
                for (int w = 0; w < 8; w++) s2 += sm->hist[w*HSTR + tid];
                sm->histc[tid] = s2;
            }
            __syncthreads();
            if (tid < 32) {
                const int base = 255 - tid*8;
                int binv[8]; int s0 = 0;
#pragma unroll
                for (int i = 0; i < 8; i++) { binv[i] = sm->histc[base - i]; s0 += binv[i]; }
                int pre = s0;
#pragma unroll
                for (int off = 1; off < 32; off <<= 1) {
                    int o = __shfl_up_sync(0xffffffffu, pre, off);
                    if (tid >= off) pre += o;
                }
                int excl = pre - s0;
                int rem = sm->s_rem;
                if ((excl < rem) && (pre >= rem)) {
                    int cum = excl; int dg = base; int nrem = rem;
#pragma unroll
                    for (int i = 0; i < 8; i++) {
                        if (cum + binv[i] >= rem) { dg = base - i; nrem = rem - cum; break; }
                        cum += binv[i];
                    }
                    sm->s_prefix = pref | ((unsigned)dg << sh);
                    sm->s_rem = nrem;
                }
            }
            __syncthreads();
        }

        const unsigned uT = sm->s_prefix;   // byte0 = 0 -> bin lower bound
        const float Tv = __uint_as_float(uT);
        const int k = sm->s_k;
        double sg = 0.0; int cg = 0;
        for (int d = tid; d < DD; d += 256) {
            float v = sm->sce[d];
            if (__float_as_uint(v) > uT) { sg += (double)v; cg++; }
        }
#pragma unroll
        for (int s = 16; s > 0; s >>= 1) {
            sg += __shfl_down_sync(0xffffffffu, sg, s);
            cg += __shfl_down_sync(0xffffffffu, cg, s);
        }
        if (lane == 0) { sm->wsg[wid] = sg; sm->wcg[wid] = cg; }
        __syncthreads();
        if (tid == 0) {
            double tsg = 0.0; int tcg = 0;
#pragma unroll
            for (int w = 0; w < 8; w++) { tsg += sm->wsg[w]; tcg += sm->wcg[w]; }
            d_topksum[b] = tsg + (double)(k - tcg) * (double)Tv;
        }
    } else {
        SMAP* sm = (SMAP*)sbuf;
        const int task = blockIdx.x - BB;      // 0..NPART-1
        const int b = task / NCE, c = task % NCE;
        const int d = c*256 + tid;
        {
            int lo = 0, to = 0;
            for (int i = tid; i < NPART; i += 256) {
                int v = d_npb[i];
                to += v;
                if (i < task) lo += v;
            }
#pragma unroll
            for (int s = 16; s > 0; s >>= 1) {
                lo += __shfl_down_sync(0xffffffffu, lo, s);
                to += __shfl_down_sync(0xffffffffu, to, s);
            }
            if (lane == 0) { sm->wlo[wid] = lo; sm->wto[wid] = to; }
            __syncthreads();
            if (tid == 0) {
                int a = 0, t2 = 0;
#pragma unroll
                for (int w = 0; w < 8; w++) { a += sm->wlo[w]; t2 += sm->wto[w]; }
                sm->s_off = a; sm->s_tot = t2;
            }
            __syncthreads();
        }
        const int s_off = sm->s_off, s_tot = sm->s_tot;
        if (s_off >= KK && !(b == 0 && c == 0)) return;

        unsigned char ct = 0;
        bool pos = false;
        if (d < DD) { ct = d_ct[(size_t)b*DD + d]; pos = (ct & 31) > 0; }

        unsigned bal = __ballot_sync(0xffffffffu, pos);
        int wpre = __popc(bal & ((1u << lane) - 1u));
        if (lane == 0) sm->wcnt[wid] = __popc(bal);
        __syncthreads();
        if (tid == 0) {
            int a = 0;
#pragma unroll
            for (int w = 0; w < 8; w++) { sm->woff[w] = a; a += sm->wcnt[w]; }
        }
        __syncthreads();
        int rank = s_off + sm->woff[wid] + wpre;
        if (pos && rank < KK) {
            d_slot[rank] = make_int2(b*DD + d, (int)ct | (1 << 8));
        }

        if (b == 0 && c == 0 && s_tot < KK) {
            __syncthreads();
            bool neg = !pos;                 // d == tid < 256
            unsigned bal2 = __ballot_sync(0xffffffffu, neg);
            int wpre2 = __popc(bal2 & ((1u << lane) - 1u));
            if (lane == 0) sm->wcnt2[wid] = __popc(bal2);
            __syncthreads();
            if (tid == 0) {
                int a = 0;
#pragma unroll
                for (int w = 0; w < 8; w++) { sm->woff2[w] = a; a += sm->wcnt2[w]; }
            }
            __syncthreads();
            int nrank = s_tot + sm->woff2[wid] + wpre2;
            if (neg && nrank < KK) {
                d_slot[nrank] = make_int2(d, (int)ct);
            }
        }
    }
}

// ---------------- kernel 4: pairstrip (R14 body) + last-block final ----------------
__global__ void k_pairfinal(const float* __restrict__ line,
                            const float* __restrict__ tgt,
                            float* __restrict__ out) {
    const int i = blockIdx.x, j = threadIdx.x;
    const int wid = j >> 5, lane = j & 31;
    __shared__ float semb[KK*LL];
    __shared__ int ssrc[KK];
    __shared__ int sy[KK];
    __shared__ float ni[LL], qi[3];
    __shared__ int labi, vali;
    __shared__ float sdist[KK];
    __shared__ unsigned pm[8], nm[8];
    __shared__ int pj[KK];
    __shared__ int npj;
    __shared__ int pwoff[8];
    __shared__ double wdk[8], wls[8];
    __shared__ int wcp[8], wcn[8], wlc[8];
    __shared__ int s_last;

    {
        int2 s = d_slot[j];
        ssrc[j] = s.x; sy[j] = s.y;
    }
    __syncthreads();
    for (int idx = j; idx < KK*LL; idx += 256) {
        int r = idx >> 5, cc = idx & 31;
        semb[idx] = line[(size_t)ssrc[r]*LL + cc];
    }
    __syncthreads();

    // warp-parallel anchor normalization (warp 0); scalars on warp 1
    if (wid == 0) {
        float e = semb[i*LL + lane];     // LL == 32
        float sum = e*e;
#pragma unroll
        for (int o = 16; o > 0; o >>= 1) sum += __shfl_xor_sync(0xffffffffu, sum, o);
        float n = fmaxf(sqrtf(sum), 1e-12f);
        ni[lane] = e / n;
    } else if (wid == 1 && lane == 0) {
        labi = sy[i] & 31; vali = (sy[i] >> 8) & 1;
        int bi = ssrc[i] / DD;
        int ti = (sy[i] >> 5) & 7;
        const float* p = tgt + (size_t)(bi*OO + ti)*9;
        qi[0] = p[5]; qi[1] = p[6]; qi[2] = p[7];
    }
    __syncthreads();

    const float* ei = semb + i*LL;
    float ej[LL];
#pragma unroll
    for (int l = 0; l < LL; l++) ej[l] = semb[j*LL + l];
    float s = 0.0f;
#pragma unroll
    for (int l = 0; l < LL; l++) s += ej[l]*ej[l];
    float rnj = 1.0f / fmaxf(sqrtf(s), 1e-12f);

    float sq = 0.0f, esq = 0.0f;
#pragma unroll
    for (int l = 0; l < LL; l++) {
        float dn = ni[l] - ej[l]*rnj; sq  += dn*dn;
        float de = ei[l] - ej[l];     esq += de*de;
    }
    float dist = sqrtf(fmaxf(sq, 1e-12f));
    sdist[j] = dist;

    float qj[3];
    {
        int bj = ssrc[j] / DD;
        int tj = (sy[j] >> 5) & 7;
        const float* p = tgt + (size_t)(bj*OO + tj)*9;
        qj[0] = p[5]; qj[1] = p[6]; qj[2] = p[7];
    }
    float qsq = 0.0f;
#pragma unroll
    for (int c = 0; c < 3; c++) { float dq = qi[c] - qj[c]; qsq += dq*dq; }

    int valj = (sy[j] >> 8) & 1;
    bool vp   = vali && valj && (i != j);
    bool same = (labi == (sy[j] & 31));
    bool pp = vp &&  same && (dist > 0.2f);
    bool np = vp && !same && (dist < 0.8f);

    unsigned pb = __ballot_sync(0xffffffffu, pp);
    unsigned nb = __ballot_sync(0xffffffffu, np);
    if (lane == 0) { pm[wid] = pb; nm[wid] = nb; }

    double dk = pp ? (double)((esq - qsq) * (esq - qsq)) : 0.0;
    int cp = pp ? 1 : 0, cn = np ? 1 : 0;
#pragma unroll
    for (int st = 16; st > 0; st >>= 1) {
        dk += __shfl_down_sync(0xffffffffu, dk, st);
        cp += __shfl_down_sync(0xffffffffu, cp, st);
        cn += __shfl_down_sync(0xffffffffu, cn, st);
    }
    if (lane == 0) { wdk[wid] = dk; wcp[wid] = cp; wcn[wid] = cn; }
    __syncthreads();
    if (j == 0) {
        double t = 0.0; int p = 0, n = 0;
#pragma unroll
        for (int w = 0; w < 8; w++) { t += wdk[w]; p += wcp[w]; n += wcn[w]; }
        d_pdesk[i] = t; d_pnpp[i] = p; d_pnnp[i] = n;
        int a = 0;
#pragma unroll
        for (int w = 0; w < 8; w++) { pwoff[w] = a; a += __popc(pm[w]); }
        npj = a;
    }
    __syncthreads();

    if (pp) pj[pwoff[wid] + __popc(pm[wid] & ((1u << lane) - 1u))] = j;
    __syncthreads();

    int n = npj;
    if (n > 0) {
        bool isneg = (nm[wid] >> lane) & 1u;
        double ls = 0.0;
        int lc = 0;
        if (isneg) {
            float dk2 = sdist[j];
            for (int a = 0; a < n; a++) {
                float l = sdist[pj[a]] - dk2 + 0.2f;
                if (l > 0.0f) { ls += (double)l; lc++; }
            }
        }
#pragma unroll
        for (int st = 16; st > 0; st >>= 1) {
            ls += __shfl_down_sync(0xffffffffu, ls, st);
            lc += __shfl_down_sync(0xffffffffu, lc, st);
        }
        if (lane == 0) { wls[wid] = ls; wlc[wid] = lc; }
        __syncthreads();
        if (j == 0) {
            double t = 0.0; int c = 0;
#pragma unroll
            for (int w = 0; w < 8; w++) { t += wls[w]; c += wlc[w]; }
            d_ptrips[i] = t; d_ptc[i] = c;
        }
    } else if (j == 0) {
        d_ptrips[i] = 0.0; d_ptc[i] = 0;
    }

    // ---- last-block final reduction ----
    if (j == 0) {
        __threadfence();
        unsigned t = atomicAdd(&g_done, 1u);
        s_last = (t == KK - 1u) ? 1 : 0;
    }
    __syncthreads();
    if (!s_last) return;
    __threadfence();

    double ll = 0.0, lp = 0.0, ce = 0.0;
    int np2 = 0;
    for (int k = j; k < NPART; k += 256) {
        ll += d_pll[k]; lp += d_plp[k]; ce += d_pce[k]; np2 += d_npb[k];
    }
    double dsk, trp;
    int npp, nnp, tc;
    {
        int k = j;   // KK == 256 == blockDim
        dsk = *(volatile double*)&d_pdesk[k];
        trp = *(volatile double*)&d_ptrips[k];
        npp = *(volatile int*)&d_pnpp[k];
        nnp = *(volatile int*)&d_pnnp[k];
        tc  = *(volatile int*)&d_ptc[k];
    }
    if (j < BB) ce += d_topksum[j];

#pragma unroll
    for (int s2 = 16; s2 > 0; s2 >>= 1) {
        ll += __shfl_down_sync(0xffffffffu, ll, s2);
        lp += __shfl_down_sync(0xffffffffu, lp, s2);
        ce += __shfl_down_sync(0xffffffffu, ce, s2);
        np2 += __shfl_down_sync(0xffffffffu, np2, s2);
        dsk += __shfl_down_sync(0xffffffffu, dsk, s2);
        trp += __shfl_down_sync(0xffffffffu, trp, s2);
        npp += __shfl_down_sync(0xffffffffu, npp, s2);
        nnp += __shfl_down_sync(0xffffffffu, nnp, s2);
        tc  += __shfl_down_sync(0xffffffffu, tc, s2);
    }
    __shared__ double sll[8], slp[8], sce2[8], sdsk[8], strp[8];
    __shared__ int snp[8], snpp[8], snnp[8], stc[8];
    if (lane == 0) {
        sll[wid] = ll; slp[wid] = lp; sce2[wid] = ce; snp[wid] = np2;
        sdsk[wid] = dsk; strp[wid] = trp; snpp[wid] = npp; snnp[wid] = nnp; stc[wid] = tc;
    }
    __syncthreads();
    if (j == 0) {
        for (int w = 1; w < 8; w++) {
            sll[0] += sll[w]; slp[0] += slp[w]; sce2[0] += sce2[w]; snp[0] += snp[w];
            sdsk[0] += sdsk[w]; strp[0] += strp[w];
            snpp[0] += snpp[w]; snnp[0] += snnp[w]; stc[0] += stc[w];
        }
        double N = (double)snp[0];
        if (N < 1.0) N = 1.0;
        double lossl = sll[0] / N;
        double lossc = sce2[0] / N;
        double lossp = slp[0] / N;

        double dnpp = (snpp[0] < 1) ? 1.0 : (double)snpp[0];
        double losst = strp[0] / (double)((stc[0] < 1) ? 1 : stc[0]);
        long long pn = (long long)snpp[0] + (long long)snnp[0];
        double dpn = (pn < 1) ? 1.0 : (double)pn;

        double ldesk = sdsk[0] / dnpp + losst / dpn;
        ldesk = ldesk / dnpp / 32.0;

        out[0] = (float)lossl;
        out[1] = (float)lossc;
        out[2] = (float)lossp;
        out[3] = (float)ldesk;
        out[4] = (float)losst;

        g_done = 0u;   // reset for next replay
    }
}

// ---------------- host launcher ----------------
extern "C" void kernel_launch(void* const* d_in, const int* in_sizes, int n_in,
                              void* d_out, int out_size) {
    const float *loc = 0, *conf = 0, *line = 0, *pose = 0, *dbox = 0, *tgt = 0;
    for (int i = 0; i < n_in; i++) {
        switch (in_sizes[i]) {
            case BB*DD*4:  loc  = (const float*)d_in[i]; break;
            case BB*DD*CC: conf = (const float*)d_in[i]; break;
            case BB*DD*LL: line = (const float*)d_in[i]; break;
            case BB*DD*3:  pose = (const float*)d_in[i]; break;
            case DD*4:     dbox = (const float*)d_in[i]; break;
            case BB*OO*9:  tgt  = (const float*)d_in[i]; break;
            default: break;
        }
    }
    if (!loc)  loc  = (const float*)d_in[0];
    if (!conf) conf = (const float*)d_in[1];
    if (!line) line = (const float*)d_in[2];
    if (!pose) pose = (const float*)d_in[3];
    if (!dbox) dbox = (const float*)d_in[4];
    if (!tgt)  tgt  = (const float*)d_in[5];

    k_lsematch<<<dim3(NCE, BB), 256>>>(conf, dbox, tgt);
    k_encce<<<dim3(NCE, BB), 256>>>(loc, pose, dbox, tgt, conf);
    k_topkmap<<<BB + NPART, 256>>>();
    k_pairfinal<<<KK, 256>>>(line, tgt, (float*)d_out);
}

// round 17
// speedup vs baseline: 1.2554x; 1.2554x over previous
#include <cuda_runtime.h>
#include <cuda_bf16.h>
#include <math.h>

#define BB 32
#define DD 8732
#define OO 8
#define CC 21
#define LL 32
#define LP 33      // padded row stride (bank-conflict-free)
#define KK 256
#define NCE 35     // chunks per batch (35*256 >= 8732)
#define NPART (BB*NCE)
#define HSTR 257   // padded per-warp histogram stride

// ---------------- device scratch ----------------
__device__ unsigned char d_ct[BB*DD];
__device__ float  d_ceneg[BB*DD];
__device__ unsigned long long d_bestkey[NPART*OO];
__device__ double d_pll[NPART], d_plp[NPART], d_pce[NPART];
__device__ int    d_npb[NPART];
__device__ double d_topksum[BB];
__device__ double d_pdesk[KK], d_ptrips[KK];
__device__ int    d_pnpp[KK], d_pnnp[KK], d_ptc[KK];
__device__ int2   d_slot[KK];

// fast exp on the FMA pipe (inputs are x - max <= 0)
__device__ __forceinline__ float fexp(float x) {
    x = fmaxf(x, -80.0f);
    float y = x * 1.442695040888963f;
    float n = rintf(y);
    float f = y - n;
    float p = 1.54035303933816e-4f;
    p = fmaf(p, f, 1.33335581464284e-3f);
    p = fmaf(p, f, 9.61812910762848e-3f);
    p = fmaf(p, f, 5.55041086648216e-2f);
    p = fmaf(p, f, 2.40226506959101e-1f);
    p = fmaf(p, f, 6.93147180559945e-1f);
    p = fmaf(p, f, 1.0f);
    return __int_as_float(__float_as_int(p) + (((int)n) << 23));
}

// ---------------- kernel 1: lse + per-chunk match keys ----------------
__global__ void k_lsematch(const float* __restrict__ conf,
                           const float* __restrict__ dbox,
                           const float* __restrict__ tgt) {
    const int b = blockIdx.y, c = blockIdx.x;
    const int tid = threadIdx.x;
    const int d = c*256 + tid;
    __shared__ float sconf[256*CC];
    __shared__ float tx1[OO], ty1[OO], tx2[OO], ty2[OO], ta[OO];

    if (tid < OO) {
        const float* p = tgt + (size_t)(b*OO + tid)*9;
        tx1[tid] = p[0]; ty1[tid] = p[1]; tx2[tid] = p[2]; ty2[tid] = p[3];
        ta[tid]  = (p[2]-p[0])*(p[3]-p[1]);
    }
    {
        int d0 = c * 256;
        int nblk = DD - d0; if (nblk > 256) nblk = 256;
        int nflt = nblk * CC;
        const float4* c4 = (const float4*)(conf + ((size_t)b*DD + d0)*CC);
        float4* s4 = (float4*)sconf;
        for (int i = tid; i < (nflt >> 2); i += 256) s4[i] = c4[i];
    }
    __syncthreads();

    unsigned long long bk[OO];
#pragma unroll
    for (int t = 0; t < OO; t++) bk[t] = 0ull;

    if (d < DD) {
        const float* v = sconf + tid*CC;
        float m = v[0];
#pragma unroll
        for (int cc = 1; cc < CC; cc++) m = fmaxf(m, v[cc]);
        float s = 0.0f;
#pragma unroll
        for (int cc = 0; cc < CC; cc++) s += fexp(v[cc] - m);
        d_ceneg[(size_t)b*DD + d] = m + logf(s) - v[0];

        float4 db = __ldg((const float4*)(dbox + d*4));
        float px1 = db.x - db.z*0.5f, py1 = db.y - db.w*0.5f;
        float px2 = db.x + db.z*0.5f, py2 = db.y + db.w*0.5f;
        float pa = (px2-px1)*(py2-py1);
#pragma unroll
        for (int t = 0; t < OO; t++) {
            float ix = fmaxf(fminf(tx2[t], px2) - fmaxf(tx1[t], px1), 0.0f);
            float iy = fmaxf(fminf(ty2[t], py2) - fmaxf(ty1[t], py1), 0.0f);
            float inter = ix * iy;
            float iou = inter / (ta[t] + pa - inter);
            bk[t] = ((unsigned long long)__float_as_uint(iou) << 32) |
                    (unsigned long long)(0xFFFFFFFFu - (unsigned)d);
        }
    }

    __shared__ unsigned long long wk[8][OO];
    int wid = tid >> 5, lane = tid & 31;
#pragma unroll
    for (int t = 0; t < OO; t++) {
        unsigned long long k = bk[t];
#pragma unroll
        for (int s = 16; s > 0; s >>= 1) {
            unsigned long long o = __shfl_down_sync(0xffffffffu, k, s);
            if (o > k) k = o;
        }
        if (lane == 0) wk[wid][t] = k;
    }
    __syncthreads();
    if (tid < OO) {
        unsigned long long k = 0ull;
#pragma unroll
        for (int w = 0; w < 8; w++) if (wk[w][tid] > k) k = wk[w][tid];
        d_bestkey[((size_t)b*NCE + c)*OO + tid] = k;
    }
}

// ---------------- kernel 2: encce ----------------
__global__ void k_encce(const float* __restrict__ loc,
                        const float* __restrict__ pose,
                        const float* __restrict__ dbox,
                        const float* __restrict__ tgt,
                        const float* __restrict__ conf) {
    const int b = blockIdx.y;
    const int tid = threadIdx.x;
    const int d = blockIdx.x * 256 + tid;

    __shared__ float tx1[OO], ty1[OO], tx2[OO], ty2[OO], ta[OO];
    __shared__ float tpz[OO][3];
    __shared__ int   tlab[OO], bestd[OO];

    if (tid < OO) {
        const float* p = tgt + (size_t)(b*OO + tid)*9;
        tx1[tid] = p[0]; ty1[tid] = p[1]; tx2[tid] = p[2]; ty2[tid] = p[3];
        ta[tid]  = (p[2]-p[0])*(p[3]-p[1]);
        tlab[tid] = (int)p[4];
        tpz[tid][0] = p[5]; tpz[tid][1] = p[6]; tpz[tid][2] = p[7];
        unsigned long long k = 0ull;
        for (int c = 0; c < NCE; c++) {
            unsigned long long o = d_bestkey[((size_t)b*NCE + c)*OO + tid];
            if (o > k) k = o;
        }
        bestd[tid] = (int)(0xFFFFFFFFu - (unsigned)(k & 0xFFFFFFFFull));
    }
    __syncthreads();

    float ll = 0.0f, lp = 0.0f, cepos = 0.0f;
    int np = 0;
    if (d < DD) {
        int idx = b*DD + d;
        float4 db = __ldg((const float4*)(dbox + d*4));
        float px1 = db.x - db.z*0.5f, py1 = db.y - db.w*0.5f;
        float px2 = db.x + db.z*0.5f, py2 = db.y + db.w*0.5f;
        float pa = (px2-px1)*(py2-py1);
        float mv = -1.0f; int mt = 0;
#pragma unroll
        for (int t = 0; t < OO; t++) {
            float ix = fmaxf(fminf(tx2[t], px2) - fmaxf(tx1[t], px1), 0.0f);
            float iy = fmaxf(fminf(ty2[t], py2) - fmaxf(ty1[t], py1), 0.0f);
            float inter = ix * iy;
            float iou = inter / (ta[t] + pa - inter);
            if (iou > mv) { mv = iou; mt = t; }
        }
#pragma unroll
        for (int t = 0; t < OO; t++) {
            if (bestd[t] == d) { mv = 2.0f; mt = t; }
        }
        int cf = (mv < 0.5f) ? 0 : (tlab[mt] + 1);
        d_ct[idx] = (unsigned char)(cf | (mt << 5));

        if (cf > 0) {
            np = 1;
            float g0 = ((tx1[mt] + tx2[mt])*0.5f - db.x) / (0.1f * db.z);
            float g1 = ((ty1[mt] + ty2[mt])*0.5f - db.y) / (0.1f * db.w);
            float g2 = logf((tx2[mt] - tx1[mt]) / db.z) / 0.2f;
            float g3 = logf((ty2[mt] - ty1[mt]) / db.w) / 0.2f;
            float g[4] = {g0, g1, g2, g3};
#pragma unroll
            for (int i = 0; i < 4; i++) {
                float dd_ = loc[(size_t)idx*4 + i] - g[i];
                float ad = fabsf(dd_);
                ll += (ad < 1.0f) ? (0.5f*dd_*dd_) : (ad - 0.5f);
            }
#pragma unroll
            for (int i = 0; i < 3; i++) {
                float e = pose[(size_t)idx*3 + i] - tpz[mt][i];
                lp += e*e;
            }
            float vneg = d_ceneg[idx];
            float v0  = __ldg(conf + (size_t)idx*CC);
            float vcf = __ldg(conf + (size_t)idx*CC + cf);
            cepos = vneg + v0 - vcf;
            d_ceneg[idx] = 0.0f;
        }
    }

    double rll = (double)ll, rlp = (double)lp, rce = (double)cepos;
    int rnp = np;
#pragma unroll
    for (int s = 16; s > 0; s >>= 1) {
        rll += __shfl_down_sync(0xffffffffu, rll, s);
        rlp += __shfl_down_sync(0xffffffffu, rlp, s);
        rce += __shfl_down_sync(0xffffffffu, rce, s);
        rnp += __shfl_down_sync(0xffffffffu, rnp, s);
    }
    __shared__ double wll[8], wlp[8], wce[8];
    __shared__ int wnp[8];
    int wid = tid >> 5, lane = tid & 31;
    if (lane == 0) { wll[wid] = rll; wlp[wid] = rlp; wce[wid] = rce; wnp[wid] = rnp; }
    __syncthreads();
    if (tid == 0) {
        double a = 0.0, b2 = 0.0, c2 = 0.0; int nn = 0;
#pragma unroll
        for (int w = 0; w < 8; w++) { a += wll[w]; b2 += wlp[w]; c2 += wce[w]; nn += wnp[w]; }
        int part = b*NCE + blockIdx.x;
        d_pll[part] = a; d_plp[part] = b2; d_pce[part] = c2;
        d_npb[part] = nn;
    }
}

// ---------------- kernel 3: topk ----------------
__global__ void __launch_bounds__(1024) k_topk() {
    const int b = blockIdx.x, tid = threadIdx.x;
    const int T = 1024;
    const int wid = tid >> 5, lane = tid & 31;
    __shared__ float sce[DD];
    __shared__ int hist[32*HSTR];
    __shared__ int histc[256];
    __shared__ unsigned s_prefix;
    __shared__ int s_rem;
    __shared__ int s_k;

    if (tid < 32) {
        int s = (tid < NCE) ? d_npb[b*NCE + tid] : 0;
        if (tid + 32 < NCE) s += d_npb[b*NCE + tid + 32];
#pragma unroll
        for (int st = 16; st > 0; st >>= 1) s += __shfl_down_sync(0xffffffffu, s, st);
        if (tid == 0) {
            int k = s * 3; if (k > DD) k = DD;
            s_k = k; s_prefix = 0u; s_rem = k;
        }
    }
    {
        const float4* ce4 = (const float4*)(d_ceneg + (size_t)b * DD);
        float4* s4 = (float4*)sce;
        for (int i = tid; i < DD/4; i += T) s4[i] = ce4[i];
    }
    __syncthreads();
    if (s_k <= 0) { if (tid == 0) d_topksum[b] = 0.0; return; }

#pragma unroll
    for (int pass = 3; pass >= 1; pass--) {
        for (int i = tid; i < 32*HSTR; i += T) hist[i] = 0;
        __syncthreads();
        const unsigned pref = s_prefix;
        const int sh = pass * 8;
        int* myhist = hist + wid*HSTR;
        for (int d = tid; d < DD; d += T) {
            unsigned u = __float_as_uint(sce[d]);
            bool ok = (pass == 3) || ((u >> (sh + 8)) == (pref >> (sh + 8)));
            if (ok) {
                int dig = (u >> sh) & 255;
                unsigned act = __activemask();
                unsigned mm = __match_any_sync(act, dig);
                if (lane == (__ffs(mm) - 1))
                    atomicAdd(&myhist[dig], __popc(mm));
            }
        }
        __syncthreads();
        if (tid < 256) {
            int s = 0;
#pragma unroll
            for (int w = 0; w < 32; w++) s += hist[w*HSTR + tid];
            histc[tid] = s;
        }
        __syncthreads();
        if (tid < 32) {
            const int base = 255 - tid*8;
            int binv[8]; int s0 = 0;
#pragma unroll
            for (int i = 0; i < 8; i++) { binv[i] = histc[base - i]; s0 += binv[i]; }
            int pre = s0;
#pragma unroll
            for (int off = 1; off < 32; off <<= 1) {
                int o = __shfl_up_sync(0xffffffffu, pre, off);
                if (tid >= off) pre += o;
            }
            int excl = pre - s0;
            int rem = s_rem;
            if ((excl < rem) && (pre >= rem)) {
                int cum = excl; int dg = base; int nrem = rem;
#pragma unroll
                for (int i = 0; i < 8; i++) {
                    if (cum + binv[i] >= rem) { dg = base - i; nrem = rem - cum; break; }
                    cum += binv[i];
                }
                s_prefix = pref | ((unsigned)dg << sh);
                s_rem = nrem;
            }
        }
        __syncthreads();
    }

    const unsigned uT = s_prefix;
    const float Tv = __uint_as_float(uT);
    const int k = s_k;
    double sg = 0.0; int cg = 0;
    for (int d = tid; d < DD; d += T) {
        float v = sce[d];
        if (__float_as_uint(v) > uT) { sg += (double)v; cg++; }
    }
#pragma unroll
    for (int s = 16; s > 0; s >>= 1) {
        sg += __shfl_down_sync(0xffffffffu, sg, s);
        cg += __shfl_down_sync(0xffffffffu, cg, s);
    }
    __shared__ double wsg[32];
    __shared__ int wcg[32];
    if (lane == 0) { wsg[wid] = sg; wcg[wid] = cg; }
    __syncthreads();
    if (tid == 0) {
        double tsg = 0.0; int tcg = 0;
        for (int i = 0; i < 32; i++) { tsg += wsg[i]; tcg += wcg[i]; }
        d_topksum[b] = tsg + (double)(k - tcg) * (double)Tv;
    }
}

// ---------------- kernel 4: slot map ----------------
__global__ void k_map() {
    const int b = blockIdx.y, c = blockIdx.x;
    const int tid = threadIdx.x;
    const int d = c*256 + tid;
    const int flatChunk = b*NCE + c;
    const int wid = tid >> 5, lane = tid & 31;

    __shared__ int s_off, s_tot;
    {
        int lo = 0, to = 0;
        for (int i = tid; i < NPART; i += 256) {
            int v = d_npb[i];
            to += v;
            if (i < flatChunk) lo += v;
        }
#pragma unroll
        for (int s = 16; s > 0; s >>= 1) {
            lo += __shfl_down_sync(0xffffffffu, lo, s);
            to += __shfl_down_sync(0xffffffffu, to, s);
        }
        __shared__ int wlo[8], wto[8];
        if (lane == 0) { wlo[wid] = lo; wto[wid] = to; }
        __syncthreads();
        if (tid == 0) {
            int a = 0, t2 = 0;
#pragma unroll
            for (int w = 0; w < 8; w++) { a += wlo[w]; t2 += wto[w]; }
            s_off = a; s_tot = t2;
        }
        __syncthreads();
    }
    if (s_off >= KK && !(b == 0 && c == 0)) return;

    unsigned char ct = 0;
    bool pos = false;
    if (d < DD) { ct = d_ct[(size_t)b*DD + d]; pos = (ct & 31) > 0; }

    unsigned bal = __ballot_sync(0xffffffffu, pos);
    int wpre = __popc(bal & ((1u << lane) - 1u));
    __shared__ int wcnt[8], woff[8];
    if (lane == 0) wcnt[wid] = __popc(bal);
    __syncthreads();
    if (tid == 0) {
        int a = 0;
#pragma unroll
        for (int w = 0; w < 8; w++) { woff[w] = a; a += wcnt[w]; }
    }
    __syncthreads();
    int rank = s_off + woff[wid] + wpre;
    if (pos && rank < KK) {
        d_slot[rank] = make_int2(b*DD + d, (int)ct | (1 << 8));
    }

    if (b == 0 && c == 0 && s_tot < KK) {
        __syncthreads();
        bool neg = !pos;
        unsigned bal2 = __ballot_sync(0xffffffffu, neg);
        int wpre2 = __popc(bal2 & ((1u << lane) - 1u));
        __shared__ int wcnt2[8], woff2[8];
        if (lane == 0) wcnt2[wid] = __popc(bal2);
        __syncthreads();
        if (tid == 0) {
            int a = 0;
#pragma unroll
            for (int w = 0; w < 8; w++) { woff2[w] = a; a += wcnt2[w]; }
        }
        __syncthreads();
        int nrank = s_tot + woff2[wid] + wpre2;
        if (neg && nrank < KK) {
            d_slot[nrank] = make_int2(d, (int)ct);
        }
    }
}

// ---------------- kernel 5: pairstrip (padded smem, grid 256) ----------------
__global__ void __launch_bounds__(256) k_pairstrip(const float* __restrict__ line,
                                                   const float* __restrict__ tgt) {
    const int i = blockIdx.x, j = threadIdx.x;
    const int wid = j >> 5, lane = j & 31;
    __shared__ float semb[KK*LP];          // padded rows: bank-conflict-free
    __shared__ int ssrc[KK];
    __shared__ int sy[KK];
    __shared__ float ni[LL], qi[3];
    __shared__ int labi, vali;
    __shared__ float sdist[KK];
    __shared__ unsigned pm[8], nm[8];
    __shared__ int pj[KK];
    __shared__ int npj;
    __shared__ int pwoff[8];
    __shared__ double wdk[8], wls[8];
    __shared__ int wcp[8], wcn[8], wlc[8];

    {
        int2 s = d_slot[j];
        ssrc[j] = s.x; sy[j] = s.y;
    }
    __syncthreads();
    for (int idx = j; idx < KK*LL; idx += 256) {
        int r = idx >> 5, cc = idx & 31;
        semb[r*LP + cc] = line[(size_t)ssrc[r]*LL + cc];
    }
    __syncthreads();

    // warp-parallel anchor normalization (warp 0); scalars on warp 1
    if (wid == 0) {
        float e = semb[i*LP + lane];     // LL == 32
        float sum = e*e;
#pragma unroll
        for (int o = 16; o > 0; o >>= 1) sum += __shfl_xor_sync(0xffffffffu, sum, o);
        float n = fmaxf(sqrtf(sum), 1e-12f);
        ni[lane] = e / n;
    } else if (wid == 1 && lane == 0) {
        labi = sy[i] & 31; vali = (sy[i] >> 8) & 1;
        int bi = ssrc[i] / DD;
        int ti = (sy[i] >> 5) & 7;
        const float* p = tgt + (size_t)(bi*OO + ti)*9;
        qi[0] = p[5]; qi[1] = p[6]; qi[2] = p[7];
    }
    __syncthreads();

    const float* ei = semb + i*LP;
    float ej[LL];
#pragma unroll
    for (int l = 0; l < LL; l++) ej[l] = semb[j*LP + l];
    float s = 0.0f;
#pragma unroll
    for (int l = 0; l < LL; l++) s += ej[l]*ej[l];
    float rnj = 1.0f / fmaxf(sqrtf(s), 1e-12f);

    float sq = 0.0f, esq = 0.0f;
#pragma unroll
    for (int l = 0; l < LL; l++) {
        float dn = ni[l] - ej[l]*rnj; sq  += dn*dn;
        float de = ei[l] - ej[l];     esq += de*de;
    }
    float dist = sqrtf(fmaxf(sq, 1e-12f));
    sdist[j] = dist;

    float qj[3];
    {
        int bj = ssrc[j] / DD;
        int tj = (sy[j] >> 5) & 7;
        const float* p = tgt + (size_t)(bj*OO + tj)*9;
        qj[0] = p[5]; qj[1] = p[6]; qj[2] = p[7];
    }
    float qsq = 0.0f;
#pragma unroll
    for (int c = 0; c < 3; c++) { float dq = qi[c] - qj[c]; qsq += dq*dq; }

    int valj = (sy[j] >> 8) & 1;
    bool vp   = vali && valj && (i != j);
    bool same = (labi == (sy[j] & 31));
    bool pp = vp &&  same && (dist > 0.2f);
    bool np = vp && !same && (dist < 0.8f);

    unsigned pb = __ballot_sync(0xffffffffu, pp);
    unsigned nb = __ballot_sync(0xffffffffu, np);
    if (lane == 0) { pm[wid] = pb; nm[wid] = nb; }

    double dk = pp ? (double)((esq - qsq) * (esq - qsq)) : 0.0;
    int cp = pp ? 1 : 0, cn = np ? 1 : 0;
#pragma unroll
    for (int st = 16; st > 0; st >>= 1) {
        dk += __shfl_down_sync(0xffffffffu, dk, st);
        cp += __shfl_down_sync(0xffffffffu, cp, st);
        cn += __shfl_down_sync(0xffffffffu, cn, st);
    }
    if (lane == 0) { wdk[wid] = dk; wcp[wid] = cp; wcn[wid] = cn; }
    __syncthreads();
    if (j == 0) {
        double t = 0.0; int p = 0, n = 0;
#pragma unroll
        for (int w = 0; w < 8; w++) { t += wdk[w]; p += wcp[w]; n += wcn[w]; }
        d_pdesk[i] = t; d_pnpp[i] = p; d_pnnp[i] = n;
        int a = 0;
#pragma unroll
        for (int w = 0; w < 8; w++) { pwoff[w] = a; a += __popc(pm[w]); }
        npj = a;
    }
    __syncthreads();

    if (pp) pj[pwoff[wid] + __popc(pm[wid] & ((1u << lane) - 1u))] = j;
    __syncthreads();

    int n = npj;
    if (n == 0) {
        if (j == 0) { d_ptrips[i] = 0.0; d_ptc[i] = 0; }
        return;
    }

    bool isneg = (nm[wid] >> lane) & 1u;
    double ls = 0.0;
    int lc = 0;
    if (isneg) {
        float dk2 = sdist[j];
        for (int a = 0; a < n; a++) {
            float l = sdist[pj[a]] - dk2 + 0.2f;
            if (l > 0.0f) { ls += (double)l; lc++; }
        }
    }
#pragma unroll
    for (int st = 16; st > 0; st >>= 1) {
        ls += __shfl_down_sync(0xffffffffu, ls, st);
        lc += __shfl_down_sync(0xffffffffu, lc, st);
    }
    if (lane == 0) { wls[wid] = ls; wlc[wid] = lc; }
    __syncthreads();
    if (j == 0) {
        double t = 0.0; int c = 0;
#pragma unroll
        for (int w = 0; w < 8; w++) { t += wls[w]; c += wlc[w]; }
        d_ptrips[i] = t; d_ptc[i] = c;
    }
}

// ---------------- kernel 6: final ----------------
__global__ void k_final(float* __restrict__ out) {
    const int tid = threadIdx.x;
    double ll = 0.0, lp = 0.0, ce = 0.0;
    int np = 0;
    for (int i = tid; i < NPART; i += 256) {
        ll += d_pll[i]; lp += d_plp[i]; ce += d_pce[i]; np += d_npb[i];
    }
    double dsk = d_pdesk[tid], trp = d_ptrips[tid];
    int npp = d_pnpp[tid], nnp = d_pnnp[tid], tc = d_ptc[tid];
    if (tid < BB) ce += d_topksum[tid];

#pragma unroll
    for (int s = 16; s > 0; s >>= 1) {
        ll += __shfl_down_sync(0xffffffffu, ll, s);
        lp += __shfl_down_sync(0xffffffffu, lp, s);
        ce += __shfl_down_sync(0xffffffffu, ce, s);
        np += __shfl_down_sync(0xffffffffu, np, s);
        dsk += __shfl_down_sync(0xffffffffu, dsk, s);
        trp += __shfl_down_sync(0xffffffffu, trp, s);
        npp += __shfl_down_sync(0xffffffffu, npp, s);
        nnp += __shfl_down_sync(0xffffffffu, nnp, s);
        tc  += __shfl_down_sync(0xffffffffu, tc, s);
    }
    __shared__ double sll[8], slp[8], sce2[8], sdsk[8], strp[8];
    __shared__ int snp[8], snpp[8], snnp[8], stc[8];
    int wid = tid >> 5, lane = tid & 31;
    if (lane == 0) {
        sll[wid] = ll; slp[wid] = lp; sce2[wid] = ce; snp[wid] = np;
        sdsk[wid] = dsk; strp[wid] = trp; snpp[wid] = npp; snnp[wid] = nnp; stc[wid] = tc;
    }
    __syncthreads();
    if (tid == 0) {
        for (int w = 1; w < 8; w++) {
            sll[0] += sll[w]; slp[0] += slp[w]; sce2[0] += sce2[w]; snp[0] += snp[w];
            sdsk[0] += sdsk[w]; strp[0] += strp[w];
            snpp[0] += snpp[w]; snnp[0] += snnp[w]; stc[0] += stc[w];
        }
        double N = (double)snp[0];
        if (N < 1.0) N = 1.0;
        double lossl = sll[0] / N;
        double lossc = sce2[0] / N;
        double lossp = slp[0] / N;

        double dnpp = (snpp[0] < 1) ? 1.0 : (double)snpp[0];
        double losst = strp[0] / (double)((stc[0] < 1) ? 1 : stc[0]);
        long long pn = (long long)snpp[0] + (long long)snnp[0];
        double dpn = (pn < 1) ? 1.0 : (double)pn;

        double ldesk = sdsk[0] / dnpp + losst / dpn;
        ldesk = ldesk / dnpp / 32.0;

        out[0] = (float)lossl;
        out[1] = (float)lossc;
        out[2] = (float)lossp;
        out[3] = (float)ldesk;
        out[4] = (float)losst;
    }
}

// ---------------- host launcher ----------------
extern "C" void kernel_launch(void* const* d_in, const int* in_sizes, int n_in,
                              void* d_out, int out_size) {
    const float *loc = 0, *conf = 0, *line = 0, *pose = 0, *dbox = 0, *tgt = 0;
    for (int i = 0; i < n_in; i++) {
        switch (in_sizes[i]) {
            case BB*DD*4:  loc  = (const float*)d_in[i]; break;
            case BB*DD*CC: conf = (const float*)d_in[i]; break;
            case BB*DD*LL: line = (const float*)d_in[i]; break;
            case BB*DD*3:  pose = (const float*)d_in[i]; break;
            case DD*4:     dbox = (const float*)d_in[i]; break;
            case BB*OO*9:  tgt  = (const float*)d_in[i]; break;
            default: break;
        }
    }
    if (!loc)  loc  = (const float*)d_in[0];
    if (!conf) conf = (const float*)d_in[1];
    if (!line) line = (const float*)d_in[2];
    if (!pose) pose = (const float*)d_in[3];
    if (!dbox) dbox = (const float*)d_in[4];
    if (!tgt)  tgt  = (const float*)d_in[5];

    static cudaStream_t s2 = [](){
        cudaStream_t s; cudaStreamCreateWithFlags(&s, cudaStreamNonBlocking); return s;
    }();
    static cudaEvent_t evF = [](){
        cudaEvent_t e; cudaEventCreateWithFlags(&e, cudaEventDisableTiming); return e;
    }();
    static cudaEvent_t evJ = [](){
        cudaEvent_t e; cudaEventCreateWithFlags(&e, cudaEventDisableTiming); return e;
    }();

    k_lsematch<<<dim3(NCE, BB), 256>>>(conf, dbox, tgt);
    k_encce<<<dim3(NCE, BB), 256>>>(loc, pose, dbox, tgt, conf);

    cudaEventRecord(evF, 0);
    cudaStreamWaitEvent(s2, evF, 0);
    k_topk<<<BB, 1024, 0, s2>>>();

    k_map<<<dim3(NCE, BB), 256>>>();
    k_pairstrip<<<KK, 256>>>(line, tgt);

    cudaEventRecord(evJ, s2);
    cudaStreamWaitEvent(0, evJ, 0);
    k_final<<<1, 256>>>((float*)d_out);
}